// round 4
// baseline (speedup 1.0000x reference)
#include <cuda_runtime.h>
#include <cuda_bf16.h>

#define DFEAT 128
#define MAX_NODES 100000

// scratch (static __device__ arrays — no allocations allowed)
__device__ int    g_is64;            // 1 if edge_index is int64, 0 if int32
__device__ int    g_deg[MAX_NODES];
__device__ float  g_dinv[MAX_NODES];
__device__ float4 g_tmp4[(size_t)MAX_NODES * (DFEAT / 4)];

// ---------------------------------------------------------------------------
// Kernel 0: detect edge_index dtype. int64 little-endian with values < 2^31
// has zero high words at odd word positions; int32 data has random node ids.
// ---------------------------------------------------------------------------
__global__ void k_detect(const int* __restrict__ ei_w) {
    if (threadIdx.x == 0 && blockIdx.x == 0) {
        int zeros = 0;
        for (int i = 0; i < 64; i++)
            if (ei_w[2 * i + 1] == 0) zeros++;
        g_is64 = (zeros >= 60) ? 1 : 0;
    }
}

// ---------------------------------------------------------------------------
// Kernel 1: g_tmp = x (vectorized), zero degree counters
// ---------------------------------------------------------------------------
__global__ void k_init(const float4* __restrict__ x4, int n) {
    int idx = blockIdx.x * blockDim.x + threadIdx.x;
    int total4 = n * (DFEAT / 4);
    if (idx < total4) {
        g_tmp4[idx] = x4[idx];
    }
    if (idx < n) g_deg[idx] = 0;
}

// ---------------------------------------------------------------------------
// Kernel 2: degree count (both endpoints). ei_w is an int32 word view;
// src edge i at word i*stride, dst edge i at word (E+i)*stride.
// ---------------------------------------------------------------------------
__global__ void k_deg(const int* __restrict__ ei_w, int E) {
    int i = blockIdx.x * blockDim.x + threadIdx.x;
    if (i < E) {
        int stride = g_is64 ? 2 : 1;
        int s = ei_w[(size_t)i * stride];
        int d = ei_w[(size_t)(E + i) * stride];
        atomicAdd(&g_deg[s], 1);
        atomicAdd(&g_deg[d], 1);
    }
}

// ---------------------------------------------------------------------------
// Kernel 3: deg^{-1/2}
// ---------------------------------------------------------------------------
__global__ void k_dinv(int n) {
    int i = blockIdx.x * blockDim.x + threadIdx.x;
    if (i < n) {
        int d = g_deg[i];
        g_dinv[i] = (d > 0) ? rsqrtf((float)d) : 0.0f;
    }
}

// ---------------------------------------------------------------------------
// Kernel 4: symmetric message aggregation, warp per edge.
// g_tmp[dst] += norm * x[src];  g_tmp[src] += norm * x[dst]
// Scalar fp32 atomics; lane j handles floats {j, j+32, j+64, j+96} so each
// RED warp-instruction covers 32 consecutive floats (128 B).
// ---------------------------------------------------------------------------
__global__ void k_agg(const float* __restrict__ x,
                      const int* __restrict__ ei_w, int E) {
    int gw   = (blockIdx.x * blockDim.x + threadIdx.x) >> 5;
    int lane = threadIdx.x & 31;
    if (gw >= E) return;

    int stride = g_is64 ? 2 : 1;
    int s = __ldg(ei_w + (size_t)gw * stride);
    int d = __ldg(ei_w + (size_t)(E + gw) * stride);
    float norm = __ldg(&g_dinv[s]) * __ldg(&g_dinv[d]);

    const float* xs = x + (size_t)s * DFEAT + lane;
    const float* xd = x + (size_t)d * DFEAT + lane;
    float* ts = (float*)g_tmp4 + (size_t)s * DFEAT + lane;
    float* td = (float*)g_tmp4 + (size_t)d * DFEAT + lane;

#pragma unroll
    for (int j = 0; j < 4; j++) {
        float vs = __ldg(xs + j * 32);
        float vd = __ldg(xd + j * 32);
        atomicAdd(td + j * 32, norm * vs);
        atomicAdd(ts + j * 32, norm * vd);
    }
}

// ---------------------------------------------------------------------------
// Kernel 5: out = relu(g_tmp @ W^T + b)
// 256 threads, 32 rows per block. W is streamed through smem transposed in
// 4 chunks of 32 K-values (keeps dynamic smem at 33 KB, below the 48 KB
// no-opt-in limit). Each thread computes a 4x4 register tile.
// ---------------------------------------------------------------------------
#define WT_STRIDE 132
#define KCHUNK 32
#define GEMM_SMEM ((KCHUNK * WT_STRIDE + 32 * 128) * 4)

__global__ void k_gemm_relu(const float* __restrict__ W,
                            const float* __restrict__ b,
                            float* __restrict__ out, int n) {
    extern __shared__ float sm[];
    float* wt = sm;                       // [KCHUNK][WT_STRIDE] wt[kk][j]=W[j][k0+kk]
    float* xs = sm + KCHUNK * WT_STRIDE;  // [32][128]

    int tid = threadIdx.x;
    int row0 = blockIdx.x * 32;

    // Load 32 rows of aggregated features.
    {
        const float4* srcp = g_tmp4 + (size_t)row0 * 32;
        float4* dstp = (float4*)xs;
        int lim4 = (n - row0) * (DFEAT / 4);
        if (lim4 > 1024) lim4 = 1024;
        for (int i = tid; i < lim4; i += 256) dstp[i] = srcp[i];
    }

    int rg = tid >> 5;            // row group 0..7
    int cg = tid & 31;            // col group 0..31
    int r0 = rg * 4, c0 = cg * 4;

    float acc[4][4];
#pragma unroll
    for (int r = 0; r < 4; r++)
#pragma unroll
        for (int c = 0; c < 4; c++) acc[r][c] = 0.0f;

    for (int k0 = 0; k0 < 128; k0 += KCHUNK) {
        __syncthreads();
        // Load W chunk transposed: 128 rows x KCHUNK k-values, coalesced reads.
        for (int i = tid; i < 128 * KCHUNK; i += 256) {
            int j  = i >> 5;       // output index 0..127
            int kk = i & (KCHUNK - 1);
            wt[kk * WT_STRIDE + j] = W[j * 128 + k0 + kk];
        }
        __syncthreads();

#pragma unroll 8
        for (int kk = 0; kk < KCHUNK; kk++) {
            int k = k0 + kk;
            float4 wv = *(const float4*)(wt + kk * WT_STRIDE + c0);
            float a0 = xs[(r0 + 0) * 128 + k];
            float a1 = xs[(r0 + 1) * 128 + k];
            float a2 = xs[(r0 + 2) * 128 + k];
            float a3 = xs[(r0 + 3) * 128 + k];
            acc[0][0] += a0 * wv.x; acc[0][1] += a0 * wv.y; acc[0][2] += a0 * wv.z; acc[0][3] += a0 * wv.w;
            acc[1][0] += a1 * wv.x; acc[1][1] += a1 * wv.y; acc[1][2] += a1 * wv.z; acc[1][3] += a1 * wv.w;
            acc[2][0] += a2 * wv.x; acc[2][1] += a2 * wv.y; acc[2][2] += a2 * wv.z; acc[2][3] += a2 * wv.w;
            acc[3][0] += a3 * wv.x; acc[3][1] += a3 * wv.y; acc[3][2] += a3 * wv.z; acc[3][3] += a3 * wv.w;
        }
    }

    float4 bv = *(const float4*)(b + c0);
#pragma unroll
    for (int r = 0; r < 4; r++) {
        int row = row0 + r0 + r;
        if (row < n) {
            float4 o;
            o.x = fmaxf(acc[r][0] + bv.x, 0.0f);
            o.y = fmaxf(acc[r][1] + bv.y, 0.0f);
            o.z = fmaxf(acc[r][2] + bv.z, 0.0f);
            o.w = fmaxf(acc[r][3] + bv.w, 0.0f);
            *(float4*)(out + (size_t)row * DFEAT + c0) = o;
        }
    }
}

// ---------------------------------------------------------------------------
// kernel_launch
// inputs: 0=x [N,128] f32, 1=edge_index [2,E] int (32 or 64), 2=W [128,128], 3=b [128]
// ---------------------------------------------------------------------------
extern "C" void kernel_launch(void* const* d_in, const int* in_sizes, int n_in,
                              void* d_out, int out_size) {
    const float* x    = (const float*)d_in[0];
    const int*   ei_w = (const int*)d_in[1];   // int32 word view of edge_index
    const float* W    = (const float*)d_in[2];
    const float* b    = (const float*)d_in[3];
    float*       out  = (float*)d_out;

    int n = in_sizes[0] / DFEAT;
    int E = in_sizes[1] / 2;

    k_detect<<<1, 32>>>(ei_w);

    // init: copy x -> g_tmp, zero deg
    {
        int total4 = n * (DFEAT / 4);
        int blocks = (total4 + 255) / 256;
        k_init<<<blocks, 256>>>((const float4*)x, n);
    }
    // degree
    k_deg<<<(E + 255) / 256, 256>>>(ei_w, E);
    // deg^{-1/2}
    k_dinv<<<(n + 255) / 256, 256>>>(n);
    // aggregation: one warp per edge
    {
        long long tthreads = (long long)E * 32;
        int blocks = (int)((tthreads + 255) / 256);
        k_agg<<<blocks, 256>>>(x, ei_w, E);
    }
    // GEMM + bias + relu (33 KB dynamic smem, no opt-in needed)
    {
        int blocks = (n + 31) / 32;
        k_gemm_relu<<<blocks, 256, GEMM_SMEM>>>(W, b, out, n);
    }
}

// round 5
// speedup vs baseline: 1.3110x; 1.3110x over previous
#include <cuda_runtime.h>
#include <cuda_bf16.h>

#define DFEAT 128
#define MAX_NODES 100000
#define MAX_EDGES 650000
#define SCAN_BLK 1024

// scratch (static __device__ arrays — no allocations allowed)
__device__ int    g_is64;                       // edge_index dtype flag
__device__ int    g_deg[MAX_NODES];             // incidence counts
__device__ int    g_off[MAX_NODES];             // CSR offsets
__device__ int    g_cur[MAX_NODES];             // scatter cursors
__device__ int    g_bsum[128];                  // scan block sums
__device__ float  g_dinv[MAX_NODES];            // deg^{-1/2}
__device__ int    g_adj[2 * MAX_EDGES];         // neighbor ids
__device__ float4 g_tmp4[(size_t)MAX_NODES * (DFEAT / 4)];  // aggregated h

// ---------------------------------------------------------------------------
// Kernel 0: detect edge_index dtype (int64 has zero high words; int32 doesn't)
// ---------------------------------------------------------------------------
__global__ void k_detect(const int* __restrict__ ei_w) {
    if (threadIdx.x == 0 && blockIdx.x == 0) {
        int zeros = 0;
        for (int i = 0; i < 64; i++)
            if (ei_w[2 * i + 1] == 0) zeros++;
        g_is64 = (zeros >= 60) ? 1 : 0;
    }
}

// ---------------------------------------------------------------------------
// Kernel 1: zero degree counters
// ---------------------------------------------------------------------------
__global__ void k_zero(int n) {
    int i = blockIdx.x * blockDim.x + threadIdx.x;
    if (i < n) g_deg[i] = 0;
}

// ---------------------------------------------------------------------------
// Kernel 2: degree histogram (both endpoints)
// ---------------------------------------------------------------------------
__global__ void k_deg(const int* __restrict__ ei_w, int E) {
    int i = blockIdx.x * blockDim.x + threadIdx.x;
    if (i < E) {
        int stride = g_is64 ? 2 : 1;
        int s = ei_w[(size_t)i * stride];
        int d = ei_w[(size_t)(E + i) * stride];
        atomicAdd(&g_deg[s], 1);
        atomicAdd(&g_deg[d], 1);
    }
}

// ---------------------------------------------------------------------------
// Kernel 3a: per-block exclusive scan of deg (1024/block) + fused dinv
// ---------------------------------------------------------------------------
__global__ void k_scan1(int n) {
    __shared__ int sm[SCAN_BLK];
    int tid = threadIdx.x;
    int i = blockIdx.x * SCAN_BLK + tid;
    int v = (i < n) ? g_deg[i] : 0;
    sm[tid] = v;
    __syncthreads();
#pragma unroll
    for (int off = 1; off < SCAN_BLK; off <<= 1) {
        int t = (tid >= off) ? sm[tid - off] : 0;
        __syncthreads();
        sm[tid] += t;
        __syncthreads();
    }
    if (i < n) {
        g_off[i] = sm[tid] - v;  // exclusive
        g_dinv[i] = (v > 0) ? rsqrtf((float)v) : 0.0f;
    }
    if (tid == SCAN_BLK - 1) g_bsum[blockIdx.x] = sm[tid];
}

// ---------------------------------------------------------------------------
// Kernel 3b: exclusive scan of block sums (single block, nb <= 128)
// ---------------------------------------------------------------------------
__global__ void k_scan2(int nb) {
    __shared__ int sm[128];
    int tid = threadIdx.x;
    int v = (tid < nb) ? g_bsum[tid] : 0;
    sm[tid] = v;
    __syncthreads();
#pragma unroll
    for (int off = 1; off < 128; off <<= 1) {
        int t = (tid >= off) ? sm[tid - off] : 0;
        __syncthreads();
        sm[tid] += t;
        __syncthreads();
    }
    if (tid < nb) g_bsum[tid] = sm[tid] - v;
}

// ---------------------------------------------------------------------------
// Kernel 3c: add block offsets, init scatter cursors
// ---------------------------------------------------------------------------
__global__ void k_scan3(int n) {
    int i = blockIdx.x * blockDim.x + threadIdx.x;
    if (i < n) {
        int o = g_off[i] + g_bsum[i >> 10];
        g_off[i] = o;
        g_cur[i] = o;
    }
}

// ---------------------------------------------------------------------------
// Kernel 4: scatter neighbor ids into CSR adjacency
// ---------------------------------------------------------------------------
__global__ void k_scatter(const int* __restrict__ ei_w, int E) {
    int i = blockIdx.x * blockDim.x + threadIdx.x;
    if (i < E) {
        int stride = g_is64 ? 2 : 1;
        int s = ei_w[(size_t)i * stride];
        int d = ei_w[(size_t)(E + i) * stride];
        int ps = atomicAdd(&g_cur[s], 1);
        g_adj[ps] = d;
        int pd = atomicAdd(&g_cur[d], 1);
        g_adj[pd] = s;
    }
}

// ---------------------------------------------------------------------------
// Kernel 5: gather aggregation, warp per node. No atomics.
// h[v] = x[v] + dinv[v] * sum_nb dinv[nb] * x[nb]
// ---------------------------------------------------------------------------
__global__ void k_gather(const float4* __restrict__ x4, int n) {
    int v    = (blockIdx.x * blockDim.x + threadIdx.x) >> 5;
    int lane = threadIdx.x & 31;
    if (v >= n) return;

    int base = g_off[v];
    int deg  = g_deg[v];

    float4 acc = make_float4(0.f, 0.f, 0.f, 0.f);
    int e = 0;
    for (; e + 2 <= deg; e += 2) {
        int nb0 = __ldg(&g_adj[base + e]);
        int nb1 = __ldg(&g_adj[base + e + 1]);
        float w0 = __ldg(&g_dinv[nb0]);
        float w1 = __ldg(&g_dinv[nb1]);
        float4 v0 = __ldg(x4 + (size_t)nb0 * 32 + lane);
        float4 v1 = __ldg(x4 + (size_t)nb1 * 32 + lane);
        acc.x += w0 * v0.x + w1 * v1.x;
        acc.y += w0 * v0.y + w1 * v1.y;
        acc.z += w0 * v0.z + w1 * v1.z;
        acc.w += w0 * v0.w + w1 * v1.w;
    }
    if (e < deg) {
        int nb = __ldg(&g_adj[base + e]);
        float w = __ldg(&g_dinv[nb]);
        float4 vv = __ldg(x4 + (size_t)nb * 32 + lane);
        acc.x += w * vv.x; acc.y += w * vv.y;
        acc.z += w * vv.z; acc.w += w * vv.w;
    }

    float dv = g_dinv[v];
    float4 xv = __ldg(x4 + (size_t)v * 32 + lane);
    float4 h;
    h.x = xv.x + dv * acc.x;
    h.y = xv.y + dv * acc.y;
    h.z = xv.z + dv * acc.z;
    h.w = xv.w + dv * acc.w;
    g_tmp4[(size_t)v * 32 + lane] = h;
}

// ---------------------------------------------------------------------------
// Kernel 6: out = relu(g_tmp @ W^T + b)
// 256 threads, 64 rows per block, 8x4 register tile per thread.
// W streamed through smem transposed in 8 chunks of 16 k-values.
// smem = 16*132*4 + 64*128*4 = 41216 B (< 48 KB, no opt-in).
// ---------------------------------------------------------------------------
#define WT_STRIDE 132
#define KCHUNK 16
#define GROWS 64
#define GEMM_SMEM ((KCHUNK * WT_STRIDE + GROWS * 128) * 4)

__global__ void k_gemm_relu(const float* __restrict__ W,
                            const float* __restrict__ b,
                            float* __restrict__ out, int n) {
    extern __shared__ float sm[];
    float* wt = sm;                       // [KCHUNK][WT_STRIDE] wt[kk][j]=W[j][k0+kk]
    float* xs = sm + KCHUNK * WT_STRIDE;  // [GROWS][128]

    int tid = threadIdx.x;
    int row0 = blockIdx.x * GROWS;

    // Load up to 64 rows of aggregated features.
    {
        const float4* srcp = g_tmp4 + (size_t)row0 * 32;
        float4* dstp = (float4*)xs;
        int lim4 = (n - row0) * (DFEAT / 4);
        if (lim4 > GROWS * 32) lim4 = GROWS * 32;
        for (int i = tid; i < lim4; i += 256) dstp[i] = srcp[i];
    }

    int rg = tid >> 5;            // row group 0..7 (uniform within warp)
    int cg = tid & 31;            // col group 0..31
    int r0 = rg * 8, c0 = cg * 4;

    float acc[8][4];
#pragma unroll
    for (int r = 0; r < 8; r++)
#pragma unroll
        for (int c = 0; c < 4; c++) acc[r][c] = 0.0f;

    for (int k0 = 0; k0 < 128; k0 += KCHUNK) {
        __syncthreads();
        // Load W chunk transposed: 128 outputs x KCHUNK k-values.
        for (int i = tid; i < 128 * KCHUNK; i += 256) {
            int j  = i >> 4;           // output index 0..127
            int kk = i & (KCHUNK - 1);
            wt[kk * WT_STRIDE + j] = W[j * 128 + k0 + kk];
        }
        __syncthreads();

#pragma unroll
        for (int kk = 0; kk < KCHUNK; kk++) {
            int k = k0 + kk;
            float4 wv = *(const float4*)(wt + kk * WT_STRIDE + c0);
#pragma unroll
            for (int r = 0; r < 8; r++) {
                float a = xs[(r0 + r) * 128 + k];   // broadcast within warp
                acc[r][0] += a * wv.x;
                acc[r][1] += a * wv.y;
                acc[r][2] += a * wv.z;
                acc[r][3] += a * wv.w;
            }
        }
    }

    float4 bv = *(const float4*)(b + c0);
#pragma unroll
    for (int r = 0; r < 8; r++) {
        int row = row0 + r0 + r;
        if (row < n) {
            float4 o;
            o.x = fmaxf(acc[r][0] + bv.x, 0.0f);
            o.y = fmaxf(acc[r][1] + bv.y, 0.0f);
            o.z = fmaxf(acc[r][2] + bv.z, 0.0f);
            o.w = fmaxf(acc[r][3] + bv.w, 0.0f);
            *(float4*)(out + (size_t)row * DFEAT + c0) = o;
        }
    }
}

// ---------------------------------------------------------------------------
// kernel_launch
// inputs: 0=x [N,128] f32, 1=edge_index [2,E] int32/int64, 2=W [128,128], 3=b [128]
// ---------------------------------------------------------------------------
extern "C" void kernel_launch(void* const* d_in, const int* in_sizes, int n_in,
                              void* d_out, int out_size) {
    const float* x    = (const float*)d_in[0];
    const int*   ei_w = (const int*)d_in[1];
    const float* W    = (const float*)d_in[2];
    const float* b    = (const float*)d_in[3];
    float*       out  = (float*)d_out;

    int n = in_sizes[0] / DFEAT;
    int E = in_sizes[1] / 2;
    int nb = (n + SCAN_BLK - 1) / SCAN_BLK;

    k_detect<<<1, 32>>>(ei_w);
    k_zero<<<(n + 1023) / 1024, 1024>>>(n);
    k_deg<<<(E + 255) / 256, 256>>>(ei_w, E);
    k_scan1<<<nb, SCAN_BLK>>>(n);
    k_scan2<<<1, 128>>>(nb);
    k_scan3<<<(n + 255) / 256, 256>>>(n);
    k_scatter<<<(E + 255) / 256, 256>>>(ei_w, E);
    {
        long long tthreads = (long long)n * 32;
        int blocks = (int)((tthreads + 255) / 256);
        k_gather<<<blocks, 256>>>((const float4*)x, n);
    }
    {
        int blocks = (n + GROWS - 1) / GROWS;
        k_gemm_relu<<<blocks, 256, GEMM_SMEM>>>(W, b, out, n);
    }
}